// round 3
// baseline (speedup 1.0000x reference)
#include <cuda_runtime.h>
#include <math.h>

// Problem dims
#define BB 2
#define DD 128
#define HH 128
#define WW 128
#define CW 0.1f
#define TWO_PI 6.283185307179586f

typedef unsigned long long u64;

// ---------------------------------------------------------------------------
// f32x2 packed-FMA helpers (sm_100+): one issue slot, two FMAs.
// ---------------------------------------------------------------------------
__device__ __forceinline__ void ffma2(u64& d, u64 a, u64 b) {
    asm("fma.rn.f32x2 %0, %1, %2, %0;" : "+l"(d) : "l"(a), "l"(b));
}
__device__ __forceinline__ u64 pack2f(float lo, float hi) {
    u64 r; asm("mov.b64 %0, {%1, %2};" : "=l"(r) : "f"(lo), "f"(hi)); return r;
}
__device__ __forceinline__ void unpack2f(u64 v, float& lo, float& hi) {
    asm("mov.b64 {%0, %1}, %2;" : "=f"(lo), "=f"(hi) : "l"(v));
}

// Channels-last scratch buffers (__device__ globals, not cudaMalloc)
__device__ float g_s1[(size_t)BB * DD * HH * WW * 8];    // conv1 out, [b][d][h][w][8]
__device__ float g_s2[(size_t)BB * DD * HH * WW * 16];   // conv2 out, [b][d][h][w][16]

// ---------------------------------------------------------------------------
// Kernel 1: field modulation + conv3d(1->8) + ReLU
// co-paired f32x2: acc2[q] = (acc[2q], acc[2q+1]); a = (v,v) packed once/tap
// ---------------------------------------------------------------------------
__global__ __launch_bounds__(512, 2)
void k_conv1(const float* __restrict__ x,
             const float* __restrict__ w1,
             const float* __restrict__ b1)
{
    __shared__ __align__(16) float tile[10 * 10 * 10];  // field-premultiplied, halo 1
    __shared__ __align__(16) float wk[27 * 8];          // [tap][co] -> natural co pairs
    __shared__ float bs[8];

    const int tx = threadIdx.x, ty = threadIdx.y, tz = threadIdx.z;
    const int tid = (tz * 8 + ty) * 8 + tx;
    const int b  = blockIdx.z >> 4;
    const int z0 = (blockIdx.z & 15) << 3;
    const int y0 = blockIdx.y << 3;
    const int x0 = blockIdx.x << 3;

    if (tid < 216) {
        int tap = tid >> 3, co = tid & 7;
        wk[tid] = w1[co * 27 + tap];
    }
    if (tid < 8) bs[tid] = b1[tid];

    const float inv = TWO_PI / (float)(DD + HH + WW);
    for (int idx = tid; idx < 1000; idx += 512) {
        int lz = idx / 100, r = idx % 100, ly = r / 10, lx = r % 10;
        int gz = z0 - 1 + lz, gy = y0 - 1 + ly, gx = x0 - 1 + lx;
        float v = 0.0f;
        if (gz >= 0 && gz < DD && gy >= 0 && gy < HH && gx >= 0 && gx < WW) {
            v = x[(((size_t)b * DD + gz) * HH + gy) * WW + gx];
            float s = (float)(gz + gy + gx);
            v *= 1.0f + CW * sinf(inv * s);
        }
        tile[idx] = v;
    }
    __syncthreads();

    u64 acc2[4];
#pragma unroll
    for (int q = 0; q < 4; q++) acc2[q] = pack2f(bs[2 * q], bs[2 * q + 1]);

#pragma unroll
    for (int kz = 0; kz < 3; kz++)
#pragma unroll
        for (int ky = 0; ky < 3; ky++)
#pragma unroll
            for (int kx = 0; kx < 3; kx++) {
                float v = tile[((tz + kz) * 10 + (ty + ky)) * 10 + (tx + kx)];
                u64 vv = pack2f(v, v);
                const int tap = (kz * 3 + ky) * 3 + kx;
                ulonglong2 w0 = *(const ulonglong2*)&wk[tap * 8];
                ulonglong2 w1v = *(const ulonglong2*)&wk[tap * 8 + 4];
                ffma2(acc2[0], vv, w0.x);
                ffma2(acc2[1], vv, w0.y);
                ffma2(acc2[2], vv, w1v.x);
                ffma2(acc2[3], vv, w1v.y);
            }

    const int gz = z0 + tz, gy = y0 + ty, gx = x0 + tx;
    size_t out = ((((size_t)b * DD + gz) * HH + gy) * WW + gx) * 8;
    float r[8];
#pragma unroll
    for (int q = 0; q < 4; q++) {
        float lo, hi; unpack2f(acc2[q], lo, hi);
        r[2 * q]     = fmaxf(lo, 0.0f);
        r[2 * q + 1] = fmaxf(hi, 0.0f);
    }
    *(float4*)&g_s1[out]     = make_float4(r[0], r[1], r[2], r[3]);
    *(float4*)&g_s1[out + 4] = make_float4(r[4], r[5], r[6], r[7]);
}

// ---------------------------------------------------------------------------
// Kernel 2: conv3d(8->16) + ReLU  -- the FFMA-bound core (3456 FMA/voxel)
// ci-paired f32x2: a = natural (ci even, ci odd) pairs from the AoS tile
// (zero packing MOVs); weights pre-interleaved in smem as
// ws2[(tap*4+p)*16+co] = (w[ci=2p][co], w[ci=2p+1][co]).
// acc2[co'] = (sum even ci, sum odd ci); final ADD combines halves.
// Two passes of 8 output channels to keep regs <= 64 -> 2 blocks/SM.
// ---------------------------------------------------------------------------
__global__ __launch_bounds__(512, 2)
void k_conv2(const float* __restrict__ w2,
             const float* __restrict__ b2)
{
    __shared__ __align__(16) float tile[1000 * 8];     // 32 KB, AoS [pos][ci]
    __shared__ __align__(16) float2 ws2[27 * 4 * 16];  // 13.8 KB, [(tap*4+p)*16+co]
    __shared__ float bs[16];

    const int tx = threadIdx.x, ty = threadIdx.y, tz = threadIdx.z;
    const int tid = (tz * 8 + ty) * 8 + tx;
    const int b  = blockIdx.z >> 4;
    const int z0 = (blockIdx.z & 15) << 3;
    const int y0 = blockIdx.y << 3;
    const int x0 = blockIdx.x << 3;

    // stage interleaved weights: i = tap*64 + p*16 + co
    for (int i = tid; i < 1728; i += 512) {
        int tap = i >> 6, rr = i & 63, p = rr >> 4, co = rr & 15;
        ws2[i] = make_float2(w2[(co * 8 + 2 * p)     * 27 + tap],
                             w2[(co * 8 + 2 * p + 1) * 27 + tap]);
    }
    if (tid < 16) bs[tid] = b2[tid];

    for (int idx = tid; idx < 1000; idx += 512) {
        int lz = idx / 100, rr = idx % 100, ly = rr / 10, lx = rr % 10;
        int gz = z0 - 1 + lz, gy = y0 - 1 + ly, gx = x0 - 1 + lx;
        float4 a = make_float4(0.f, 0.f, 0.f, 0.f), c = a;
        if (gz >= 0 && gz < DD && gy >= 0 && gy < HH && gx >= 0 && gx < WW) {
            size_t base = ((((size_t)b * DD + gz) * HH + gy) * WW + gx) * 8;
            a = *(const float4*)&g_s1[base];
            c = *(const float4*)&g_s1[base + 4];
        }
        *(float4*)&tile[idx * 8]     = a;
        *(float4*)&tile[idx * 8 + 4] = c;
    }
    __syncthreads();

    const int gz = z0 + tz, gy = y0 + ty, gx = x0 + tx;
    const size_t voxout = ((((size_t)b * DD + gz) * HH + gy) * WW + gx) * 16;

#pragma unroll
    for (int pass = 0; pass < 2; pass++) {
        const int coBase = pass * 8;
        u64 acc2[8];
#pragma unroll
        for (int q = 0; q < 8; q++) acc2[q] = pack2f(bs[coBase + q], 0.0f);

#pragma unroll
        for (int kz = 0; kz < 3; kz++)
#pragma unroll
            for (int ky = 0; ky < 3; ky++)
#pragma unroll
                for (int kx = 0; kx < 3; kx++) {
                    const int tap = (kz * 3 + ky) * 3 + kx;
                    const float* ip =
                        &tile[(((tz + kz) * 10 + (ty + ky)) * 10 + (tx + kx)) * 8];
                    ulonglong2 iv0 = *(const ulonglong2*)ip;        // (ci0,ci1),(ci2,ci3)
                    ulonglong2 iv1 = *(const ulonglong2*)(ip + 4);  // (ci4,ci5),(ci6,ci7)
                    u64 a[4] = {iv0.x, iv0.y, iv1.x, iv1.y};
#pragma unroll
                    for (int p = 0; p < 4; p++) {
                        const ulonglong2* wp =
                            (const ulonglong2*)&ws2[(tap * 4 + p) * 16 + coBase];
                        ulonglong2 wA = wp[0];   // co+0, co+1
                        ulonglong2 wB = wp[1];   // co+2, co+3
                        ulonglong2 wC = wp[2];   // co+4, co+5
                        ulonglong2 wD = wp[3];   // co+6, co+7
                        ffma2(acc2[0], a[p], wA.x);
                        ffma2(acc2[1], a[p], wA.y);
                        ffma2(acc2[2], a[p], wB.x);
                        ffma2(acc2[3], a[p], wB.y);
                        ffma2(acc2[4], a[p], wC.x);
                        ffma2(acc2[5], a[p], wC.y);
                        ffma2(acc2[6], a[p], wD.x);
                        ffma2(acc2[7], a[p], wD.y);
                    }
                }

        float r[8];
#pragma unroll
        for (int q = 0; q < 8; q++) {
            float lo, hi; unpack2f(acc2[q], lo, hi);
            r[q] = fmaxf(lo + hi, 0.0f);
        }
        *(float4*)&g_s2[voxout + coBase]     = make_float4(r[0], r[1], r[2], r[3]);
        *(float4*)&g_s2[voxout + coBase + 4] = make_float4(r[4], r[5], r[6], r[7]);
    }
}

// ---------------------------------------------------------------------------
// Kernel 3: conv3d(16->1) + tanh
// ci-paired f32x2: both operands naturally paired -> zero packing
// ---------------------------------------------------------------------------
extern __shared__ __align__(16) float dyn_tile[];

__global__ __launch_bounds__(512, 2)
void k_conv3(const float* __restrict__ w3,
             const float* __restrict__ b3,
             float* __restrict__ out)
{
    __shared__ __align__(16) float ws[27 * 16];  // [tap][ci] -> natural ci pairs
    __shared__ float bsv;

    const int tx = threadIdx.x, ty = threadIdx.y, tz = threadIdx.z;
    const int tid = (tz * 8 + ty) * 8 + tx;
    const int b  = blockIdx.z >> 4;
    const int z0 = (blockIdx.z & 15) << 3;
    const int y0 = blockIdx.y << 3;
    const int x0 = blockIdx.x << 3;

    if (tid < 432) {
        int tap = tid >> 4, ci = tid & 15;
        ws[tid] = w3[ci * 27 + tap];
    }
    if (tid == 0) bsv = b3[0];

    for (int idx = tid; idx < 4000; idx += 512) {
        int pos = idx >> 2, q = idx & 3;
        int lz = pos / 100, rr = pos % 100, ly = rr / 10, lx = rr % 10;
        int gz = z0 - 1 + lz, gy = y0 - 1 + ly, gx = x0 - 1 + lx;
        float4 v = make_float4(0.f, 0.f, 0.f, 0.f);
        if (gz >= 0 && gz < DD && gy >= 0 && gy < HH && gx >= 0 && gx < WW) {
            size_t base = ((((size_t)b * DD + gz) * HH + gy) * WW + gx) * 16;
            v = *(const float4*)&g_s2[base + q * 4];
        }
        *(float4*)&dyn_tile[pos * 16 + q * 4] = v;
    }
    __syncthreads();

    u64 acc2[4];
    acc2[0] = pack2f(bsv, 0.0f);
    acc2[1] = pack2f(0.0f, 0.0f);
    acc2[2] = pack2f(0.0f, 0.0f);
    acc2[3] = pack2f(0.0f, 0.0f);

#pragma unroll
    for (int kz = 0; kz < 3; kz++)
#pragma unroll
        for (int ky = 0; ky < 3; ky++)
#pragma unroll
            for (int kx = 0; kx < 3; kx++) {
                const int tap = (kz * 3 + ky) * 3 + kx;
                const float* ip =
                    &dyn_tile[(((tz + kz) * 10 + (ty + ky)) * 10 + (tx + kx)) * 16];
                const ulonglong2* ia = (const ulonglong2*)ip;       // 4 x ulonglong2
                const ulonglong2* wa = (const ulonglong2*)&ws[tap * 16];
                ulonglong2 i0 = ia[0], i1 = ia[1], i2 = ia[2], i3 = ia[3];
                ulonglong2 w0 = wa[0], w1 = wa[1], w2v = wa[2], w3v = wa[3];
                ffma2(acc2[0], i0.x, w0.x);
                ffma2(acc2[1], i0.y, w0.y);
                ffma2(acc2[2], i1.x, w1.x);
                ffma2(acc2[3], i1.y, w1.y);
                ffma2(acc2[0], i2.x, w2v.x);
                ffma2(acc2[1], i2.y, w2v.y);
                ffma2(acc2[2], i3.x, w3v.x);
                ffma2(acc2[3], i3.y, w3v.y);
            }

    float tot = 0.0f;
#pragma unroll
    for (int q = 0; q < 4; q++) {
        float lo, hi; unpack2f(acc2[q], lo, hi);
        tot += lo + hi;
    }

    const int gz = z0 + tz, gy = y0 + ty, gx = x0 + tx;
    out[(((size_t)b * DD + gz) * HH + gy) * WW + gx] = tanhf(tot);
}

// ---------------------------------------------------------------------------
extern "C" void kernel_launch(void* const* d_in, const int* in_sizes, int n_in,
                              void* d_out, int out_size)
{
    const float* x  = (const float*)d_in[0];
    const float* w1 = (const float*)d_in[1];
    const float* b1 = (const float*)d_in[2];
    const float* w2 = (const float*)d_in[3];
    const float* b2 = (const float*)d_in[4];
    const float* w3 = (const float*)d_in[5];
    const float* b3 = (const float*)d_in[6];
    float* out = (float*)d_out;

    static bool attr_set = false;  // idempotent attribute set (not a work guard)
    if (!attr_set) {
        cudaFuncSetAttribute(k_conv3, cudaFuncAttributeMaxDynamicSharedMemorySize,
                             10 * 10 * 10 * 16 * sizeof(float));
        attr_set = true;
    }

    dim3 blk(8, 8, 8);
    dim3 grd(WW / 8, HH / 8, (DD / 8) * BB);

    k_conv1<<<grd, blk>>>(x, w1, b1);
    k_conv2<<<grd, blk>>>(w2, b2);
    k_conv3<<<grd, blk, 10 * 10 * 10 * 16 * sizeof(float)>>>(w3, b3, out);
}